// round 1
// baseline (speedup 1.0000x reference)
#include <cuda_runtime.h>
#include <math.h>

#define BB 2
#define NN 8192
#define CC 128
#define KNB 16
#define EPSF 1e-5f

// ---------------- scratch (device globals; no allocation allowed) ----------------
__device__ float g_q[BB*NN*CC];
__device__ float g_k[BB*NN*CC];
__device__ float g_v[BB*NN*CC];
__device__ int   g_idx[BB*NN*KNB];
__device__ float g_pW1f[CC*3];
__device__ float g_pb1f[CC];
__device__ float g_aW1f[CC*CC];
__device__ float g_ab1f[CC];

// ---------------- fold BN into preceding linears ----------------
__global__ void fold_kernel(const float* __restrict__ pW1, const float* __restrict__ pb1,
                            const float* __restrict__ pg,  const float* __restrict__ pbeta,
                            const float* __restrict__ pmean,const float* __restrict__ pvar,
                            const float* __restrict__ aW1, const float* __restrict__ ab1,
                            const float* __restrict__ ag,  const float* __restrict__ abeta,
                            const float* __restrict__ amean,const float* __restrict__ avar)
{
    int o = threadIdx.x;
    if (o >= CC) return;
    float s = pg[o] * rsqrtf(pvar[o] + EPSF);
    g_pW1f[o*3+0] = pW1[o*3+0] * s;
    g_pW1f[o*3+1] = pW1[o*3+1] * s;
    g_pW1f[o*3+2] = pW1[o*3+2] * s;
    g_pb1f[o] = pb1[o]*s + pbeta[o] - pmean[o]*s;

    float sa = ag[o] * rsqrtf(avar[o] + EPSF);
    for (int i = 0; i < CC; i++) g_aW1f[o*CC+i] = aW1[o*CC+i] * sa;
    g_ab1f[o] = ab1[o]*sa + abeta[o] - amean[o]*sa;
}

// ---------------- KNN: top-16 smallest squared distances ----------------
// grid = (B*N)/128 blocks of 128 threads, 1 thread = 1 query point.
__global__ void knn_kernel(const float* __restrict__ xyz)
{
    __shared__ float sx[2048], sy[2048], sz[2048], ss[2048];
    int b = blockIdx.x >> 6;                 // 64 blocks per batch
    int n = ((blockIdx.x & 63) << 7) + threadIdx.x;
    const float* base = xyz + (size_t)b * NN * 3;

    float qx = base[n*3+0], qy = base[n*3+1], qz = base[n*3+2];
    float qs = qx*qx + qy*qy + qz*qz;

    float bd[KNB]; int bi[KNB];
#pragma unroll
    for (int t = 0; t < KNB; t++) { bd[t] = 3.4e38f; bi[t] = 0; }
    float worst = 3.4e38f; int wpos = 0;

    for (int t0 = 0; t0 < NN; t0 += 2048) {
        __syncthreads();
        for (int e = threadIdx.x; e < 2048; e += 128) {
            int j = t0 + e;
            float x = base[j*3+0], y = base[j*3+1], z = base[j*3+2];
            sx[e] = x; sy[e] = y; sz[e] = z; ss[e] = x*x + y*y + z*z;
        }
        __syncthreads();
        for (int e = 0; e < 2048; e++) {
            float d = qs + ss[e] - 2.0f*(qx*sx[e] + qy*sy[e] + qz*sz[e]);
            if (d < worst) {
                int j = t0 + e;
#pragma unroll
                for (int t = 0; t < KNB; t++) if (t == wpos) { bd[t] = d; bi[t] = j; }
                worst = -3.4e38f;
#pragma unroll
                for (int t = 0; t < KNB; t++) if (bd[t] > worst) { worst = bd[t]; wpos = t; }
            }
        }
    }
    int q = b*NN + n;
#pragma unroll
    for (int t = 0; t < KNB; t++) g_idx[q*KNB + t] = bi[t];
}

// ---------------- in-block 128x128x128 GEMM helpers ----------------
// C[r][o] = sum_i A[r][i] * W[o][i]  (torch Linear convention, W row-major [out][in])
// A in smem (row stride 129). W streamed from global through a 32-wide smem tile.
// Thread map: tx = tid&15 -> o = tx + 16*oo ; ty = tid>>4 -> r = ty + 16*rr.

__device__ __forceinline__ void gemm_core(const float* __restrict__ sA,
                                          const float* __restrict__ Wg,
                                          float* __restrict__ sW,
                                          float acc[8][8])
{
    const int tid = threadIdx.x;
    const int tx = tid & 15, ty = tid >> 4;
#pragma unroll
    for (int i = 0; i < 8; i++)
#pragma unroll
        for (int j = 0; j < 8; j++) acc[i][j] = 0.0f;

    for (int i0 = 0; i0 < 128; i0 += 32) {
        __syncthreads();
#pragma unroll 4
        for (int e = tid; e < 128*32; e += 256) {
            int o = e >> 5, ic = e & 31;
            sW[ic*129 + o] = Wg[o*128 + i0 + ic];
        }
        __syncthreads();
#pragma unroll 4
        for (int ic = 0; ic < 32; ic++) {
            float a[8], w[8];
#pragma unroll
            for (int rr = 0; rr < 8; rr++) a[rr] = sA[(ty + 16*rr)*129 + i0 + ic];
#pragma unroll
            for (int oo = 0; oo < 8; oo++) w[oo] = sW[ic*129 + tx + 16*oo];
#pragma unroll
            for (int rr = 0; rr < 8; rr++)
#pragma unroll
                for (int oo = 0; oo < 8; oo++)
                    acc[rr][oo] = fmaf(a[rr], w[oo], acc[rr][oo]);
        }
    }
}

__device__ __forceinline__ void gemm_to_smem(const float* __restrict__ sA,
                                             const float* __restrict__ Wg,
                                             float* __restrict__ sW,
                                             float* __restrict__ sC,
                                             const float* __restrict__ bias,
                                             bool do_relu)
{
    const int tid = threadIdx.x;
    const int tx = tid & 15, ty = tid >> 4;
    float acc[8][8];
    gemm_core(sA, Wg, sW, acc);
    __syncthreads();
#pragma unroll
    for (int oo = 0; oo < 8; oo++) {
        int o = tx + 16*oo;
        float bv = bias ? bias[o] : 0.0f;
#pragma unroll
        for (int rr = 0; rr < 8; rr++) {
            int r = ty + 16*rr;
            float v = acc[rr][oo] + bv;
            if (do_relu) v = fmaxf(v, 0.0f);
            sC[r*129 + o] = v;
        }
    }
    __syncthreads();
}

__device__ __forceinline__ void gemm_to_gmem(const float* __restrict__ sA,
                                             const float* __restrict__ Wg,
                                             float* __restrict__ sW,
                                             float* __restrict__ gC)
{
    const int tid = threadIdx.x;
    const int tx = tid & 15, ty = tid >> 4;
    float acc[8][8];
    gemm_core(sA, Wg, sW, acc);
    __syncthreads();
#pragma unroll
    for (int oo = 0; oo < 8; oo++) {
        int o = tx + 16*oo;
#pragma unroll
        for (int rr = 0; rr < 8; rr++) {
            int r = ty + 16*rr;
            gC[(size_t)r*128 + o] = acc[rr][oo];
        }
    }
    __syncthreads();
}

// ---------------- QKV projections: q/k/v = feat @ W^T ----------------
#define QKV_SMEM ((128*129 + 32*129) * 4)
__global__ __launch_bounds__(256, 1) void qkv_kernel(const float* __restrict__ feat,
                                                     const float* __restrict__ Wq,
                                                     const float* __restrict__ Wk,
                                                     const float* __restrict__ Wv)
{
    extern __shared__ float sm[];
    float* sA = sm;             // 128 x 129
    float* sW = sm + 128*129;   // 32 x 129
    size_t row0 = (size_t)blockIdx.x * 128;
    for (int e = threadIdx.x; e < 128*128; e += 256) {
        int r = e >> 7, c = e & 127;
        sA[r*129 + c] = feat[(row0 + r)*128 + c];
    }
    __syncthreads();
    gemm_to_gmem(sA, Wq, sW, g_q + row0*128);
    gemm_to_gmem(sA, Wk, sW, g_k + row0*128);
    gemm_to_gmem(sA, Wv, sW, g_v + row0*128);
}

// ---------------- fused main kernel: 8 queries (128 pair-rows) per block ----------------
// smem words: 3*16512 (act) + 4128 (Wtile) + 1024 (q) + 1024 (out) + 384 (nbr xyz)
//           + 24 (query xyz) + 128 ints (idx)
#define MAIN_SMEM ((3*16512 + 4128 + 1024 + 1024 + 384 + 24) * 4 + 128 * 4)

__global__ __launch_bounds__(256, 1) void main_kernel(const float* __restrict__ xyz,
                                                      const float* __restrict__ pW2,
                                                      const float* __restrict__ pb2,
                                                      const float* __restrict__ aW2,
                                                      const float* __restrict__ ab2,
                                                      const float* __restrict__ Wout,
                                                      float* __restrict__ out)
{
    extern __shared__ float sm[];
    float* sA    = sm;                 // 128 x 129 : hidden / t / logits
    float* sB    = sA + 16512;         // 128 x 129 : h
    float* sP    = sB + 16512;         // 128 x 129 : pos -> v+pos
    float* sW    = sP + 16512;         // 32 x 129  : weight tile
    float* sQ    = sW + 4128;          // 8 x 128
    float* sOut  = sQ + 1024;          // 8 x 128
    float* sNx   = sOut + 1024;        // 128
    float* sNy   = sNx + 128;
    float* sNz   = sNy + 128;
    float* sQxyz = sNz + 128;          // 8 x 3
    int*   sIdx  = (int*)(sQxyz + 24); // 128

    const int tid = threadIdx.x;
    const int g0 = blockIdx.x * 8;          // first global query row (b*N + n)
    const int b  = g0 >> 13;                // / 8192
    const int n0 = g0 & (NN - 1);
    const float* xb = xyz + (size_t)b * NN * 3;

    // stage idx, q rows, query xyz
    if (tid < 128) sIdx[tid] = g_idx[(size_t)g0 * KNB + tid];
    for (int e = tid; e < 8*128; e += 256) sQ[e] = g_q[(size_t)g0 * 128 + e];
    if (tid < 24) sQxyz[tid] = xb[(size_t)n0 * 3 + tid];
    __syncthreads();
    if (tid < 128) {
        int j = sIdx[tid];
        sNx[tid] = xb[j*3+0]; sNy[tid] = xb[j*3+1]; sNz[tid] = xb[j*3+2];
    }
    __syncthreads();

    // pos hidden = relu(rel @ pW1f^T + pb1f)  -> sA
    {
        int o = tid & 127;
        float w0 = g_pW1f[o*3+0], w1 = g_pW1f[o*3+1], w2 = g_pW1f[o*3+2], bb = g_pb1f[o];
        for (int r = tid >> 7; r < 128; r += 2) {
            int qi = r >> 4;
            float rx = sNx[r] - sQxyz[qi*3+0];
            float ry = sNy[r] - sQxyz[qi*3+1];
            float rz = sNz[r] - sQxyz[qi*3+2];
            float h = fmaf(rx, w0, fmaf(ry, w1, fmaf(rz, w2, bb)));
            sA[r*129 + o] = fmaxf(h, 0.0f);
        }
    }
    __syncthreads();

    // pos = hidden @ pW2^T + pb2  -> sP
    gemm_to_smem(sA, pW2, sW, sP, pb2, false);

    // t = q - k + pos -> sA ;  vp = v + pos -> sP   (gather k,v rows)
    {
        int o = tid & 127;
        for (int r = tid >> 7; r < 128; r += 2) {
            int qi = r >> 4;
            int j = sIdx[r];
            size_t row = ((size_t)b * NN + j) * 128 + o;
            float p = sP[r*129 + o];
            sA[r*129 + o] = sQ[qi*128 + o] - g_k[row] + p;
            sP[r*129 + o] = g_v[row] + p;
        }
    }
    __syncthreads();

    // h = relu(t @ aW1f^T + ab1f) -> sB ; logits = h @ aW2^T + ab2 -> sA
    gemm_to_smem(sA, g_aW1f, sW, sB, g_ab1f, true);
    gemm_to_smem(sB, aW2,    sW, sA, ab2,    false);

    // per-channel softmax over K=16 neighbors, weighted sum of (v+pos) -> sOut
    for (int it = tid; it < 8*128; it += 256) {
        int qi = it >> 7, o = it & 127;
        int rbase = qi * 16;
        float m = -3.4e38f;
#pragma unroll
        for (int kk = 0; kk < 16; kk++) m = fmaxf(m, sA[(rbase+kk)*129 + o]);
        float s = 0.0f, acc = 0.0f;
#pragma unroll
        for (int kk = 0; kk < 16; kk++) {
            float e = expf(sA[(rbase+kk)*129 + o] - m);
            s += e;
            acc = fmaf(e, sP[(rbase+kk)*129 + o], acc);
        }
        sOut[qi*128 + o] = acc / s;
    }
    __syncthreads();

    // final: out = sOut @ Wout^T  (8 x 128 rows)
    {
        float acc[4] = {0.f, 0.f, 0.f, 0.f};
        for (int i0 = 0; i0 < 128; i0 += 32) {
            __syncthreads();
#pragma unroll 4
            for (int e = tid; e < 128*32; e += 256) {
                int o = e >> 5, ic = e & 31;
                sW[ic*129 + o] = Wout[o*128 + i0 + ic];
            }
            __syncthreads();
#pragma unroll 4
            for (int ic = 0; ic < 32; ic++) {
#pragma unroll
                for (int u = 0; u < 4; u++) {
                    int it = tid + u*256;
                    int qi = it >> 7, o = it & 127;
                    acc[u] = fmaf(sOut[qi*128 + i0 + ic], sW[ic*129 + o], acc[u]);
                }
            }
        }
#pragma unroll
        for (int u = 0; u < 4; u++) {
            int it = tid + u*256;
            int qi = it >> 7, o = it & 127;
            out[((size_t)g0 + qi) * 128 + o] = acc[u];
        }
    }
}

// ---------------- launch ----------------
extern "C" void kernel_launch(void* const* d_in, const int* in_sizes, int n_in,
                              void* d_out, int out_size)
{
    const float* xyz   = (const float*)d_in[0];
    const float* feat  = (const float*)d_in[1];
    const float* Wq    = (const float*)d_in[2];
    const float* Wk    = (const float*)d_in[3];
    const float* Wv    = (const float*)d_in[4];
    const float* pW1   = (const float*)d_in[5];
    const float* pb1   = (const float*)d_in[6];
    const float* pg    = (const float*)d_in[7];
    const float* pbeta = (const float*)d_in[8];
    const float* pmean = (const float*)d_in[9];
    const float* pvar  = (const float*)d_in[10];
    const float* pW2   = (const float*)d_in[11];
    const float* pb2   = (const float*)d_in[12];
    const float* aW1   = (const float*)d_in[13];
    const float* ab1   = (const float*)d_in[14];
    const float* ag    = (const float*)d_in[15];
    const float* abeta = (const float*)d_in[16];
    const float* amean = (const float*)d_in[17];
    const float* avar  = (const float*)d_in[18];
    const float* aW2   = (const float*)d_in[19];
    const float* ab2   = (const float*)d_in[20];
    const float* Wout  = (const float*)d_in[21];
    float* out = (float*)d_out;

    cudaFuncSetAttribute((const void*)qkv_kernel,
                         cudaFuncAttributeMaxDynamicSharedMemorySize, QKV_SMEM);
    cudaFuncSetAttribute((const void*)main_kernel,
                         cudaFuncAttributeMaxDynamicSharedMemorySize, MAIN_SMEM);

    fold_kernel<<<1, 128>>>(pW1, pb1, pg, pbeta, pmean, pvar,
                            aW1, ab1, ag, abeta, amean, avar);
    knn_kernel<<<(BB*NN)/128, 128>>>(xyz);
    qkv_kernel<<<(BB*NN)/128, 256, QKV_SMEM>>>(feat, Wq, Wk, Wv);
    main_kernel<<<(BB*NN)/8, 256, MAIN_SMEM>>>(xyz, pW2, pb2, aW2, ab2, Wout, out);
}

// round 2
// speedup vs baseline: 1.2088x; 1.2088x over previous
#include <cuda_runtime.h>
#include <math.h>

#define BB 2
#define NN 8192
#define CC 128
#define KNB 16
#define EPSF 1e-5f
#define SAS 132   // activation smem row stride (floats)
#define WKS 20    // weight-chunk smem row stride (floats), chunk K=16

// ---------------- device scratch ----------------
__device__ float g_q[BB*NN*CC];
__device__ float g_k[BB*NN*CC];
__device__ float g_v[BB*NN*CC];
__device__ int   g_idx[BB*NN*KNB];
__device__ float g_pW1f[CC*3];
__device__ float g_pb1f[CC];
__device__ float g_aW1f[CC*CC];
__device__ float g_ab1f[CC];

// ---------------- helpers ----------------
__device__ __forceinline__ unsigned tf32b(float x) {
    unsigned u; asm("cvt.rna.tf32.f32 %0, %1;" : "=r"(u) : "f"(x)); return u;
}

__device__ __forceinline__ void mma_tf32(float c[4],
                                         unsigned a0, unsigned a1, unsigned a2, unsigned a3,
                                         unsigned b0, unsigned b1) {
    asm volatile("mma.sync.aligned.m16n8k8.row.col.f32.tf32.tf32.f32 "
                 "{%0,%1,%2,%3},{%4,%5,%6,%7},{%8,%9},{%0,%1,%2,%3};"
                 : "+f"(c[0]), "+f"(c[1]), "+f"(c[2]), "+f"(c[3])
                 : "r"(a0), "r"(a1), "r"(a2), "r"(a3), "r"(b0), "r"(b1));
}

// ---------------- fold BN into preceding linears ----------------
__global__ void fold_kernel(const float* __restrict__ pW1, const float* __restrict__ pb1,
                            const float* __restrict__ pg,  const float* __restrict__ pbeta,
                            const float* __restrict__ pmean,const float* __restrict__ pvar,
                            const float* __restrict__ aW1, const float* __restrict__ ab1,
                            const float* __restrict__ ag,  const float* __restrict__ abeta,
                            const float* __restrict__ amean,const float* __restrict__ avar)
{
    int o = threadIdx.x;
    if (o >= CC) return;
    float s = pg[o] * rsqrtf(pvar[o] + EPSF);
    g_pW1f[o*3+0] = pW1[o*3+0] * s;
    g_pW1f[o*3+1] = pW1[o*3+1] * s;
    g_pW1f[o*3+2] = pW1[o*3+2] * s;
    g_pb1f[o] = pb1[o]*s + pbeta[o] - pmean[o]*s;

    float sa = ag[o] * rsqrtf(avar[o] + EPSF);
    for (int i = 0; i < CC; i++) g_aW1f[o*CC+i] = aW1[o*CC+i] * sa;
    g_ab1f[o] = ab1[o]*sa + abeta[o] - amean[o]*sa;
}

// ---------------- KNN: 2 threads per query, parity-strided candidates ----------------
// grid = 128 blocks x 256 threads; block handles 128 queries.
#define KNN_SMEM (49152)
__global__ __launch_bounds__(256, 1) void knn_kernel(const float* __restrict__ xyz)
{
    extern __shared__ float ksm[];
    float* sx = ksm;            // 2048
    float* sy = sx + 2048;
    float* sz = sy + 2048;
    float* ss = sz + 2048;
    float* sMD = ss + 2048;     // 128*16 (odd threads' lists)
    int*   sMI = (int*)(sMD + 2048);

    const int tid = threadIdx.x;
    const int qloc = tid >> 1;
    const int par  = tid & 1;
    const int b = blockIdx.x >> 6;
    const int n = ((blockIdx.x & 63) << 7) + qloc;
    const float* base = xyz + (size_t)b * NN * 3;

    float qx = base[n*3+0], qy = base[n*3+1], qz = base[n*3+2];
    float qs = qx*qx + qy*qy + qz*qz;

    float bd[KNB]; int bi[KNB];
#pragma unroll
    for (int t = 0; t < KNB; t++) { bd[t] = 3.4e38f; bi[t] = 0; }
    float worst = 3.4e38f; int wpos = 0;

    for (int t0 = 0; t0 < NN; t0 += 2048) {
        __syncthreads();
        for (int e = tid; e < 2048; e += 256) {
            int j = t0 + e;
            float x = base[j*3+0], y = base[j*3+1], z = base[j*3+2];
            sx[e] = x; sy[e] = y; sz[e] = z; ss[e] = x*x + y*y + z*z;
        }
        __syncthreads();
#pragma unroll 4
        for (int e = par; e < 2048; e += 2) {
            float d = qs + ss[e] - 2.0f*(qx*sx[e] + qy*sy[e] + qz*sz[e]);
            if (d < worst) {
                int j = t0 + e;
#pragma unroll
                for (int t = 0; t < KNB; t++) if (t == wpos) { bd[t] = d; bi[t] = j; }
                worst = -3.4e38f;
#pragma unroll
                for (int t = 0; t < KNB; t++) if (bd[t] > worst) { worst = bd[t]; wpos = t; }
            }
        }
    }
    __syncthreads();
    if (par == 1) {
#pragma unroll
        for (int t = 0; t < KNB; t++) { sMD[qloc*KNB+t] = bd[t]; sMI[qloc*KNB+t] = bi[t]; }
    }
    __syncthreads();
    if (par == 0) {
#pragma unroll
        for (int t = 0; t < KNB; t++) {
            float d = sMD[qloc*KNB+t];
            if (d < worst) {
                int j = sMI[qloc*KNB+t];
#pragma unroll
                for (int u = 0; u < KNB; u++) if (u == wpos) { bd[u] = d; bi[u] = j; }
                worst = -3.4e38f;
#pragma unroll
                for (int u = 0; u < KNB; u++) if (bd[u] > worst) { worst = bd[u]; wpos = u; }
            }
        }
        int q = b*NN + n;
#pragma unroll
        for (int t = 0; t < KNB; t++) g_idx[q*KNB + t] = bi[t];
    }
}

// ---------------- 3xTF32 128x128x128 GEMM on tensor cores ----------------
// C[r][o] = sum_i A[r][i]*W[o][i]  (torch Linear: W [out][in] row-major)
// 256 threads = 8 warps: warp (w&3) -> rows 32*(w&3)..+31 (2 m-tiles),
//                        warp (w>>2) -> cols 64*(w>>2)..+63 (8 n-tiles).
// A fp32 in smem [128][SAS]; W streamed global -> hi/lo tf32 chunks [128][WKS] (K-chunk 16).
__device__ __forceinline__ void gemm_tf32x3(const float* __restrict__ sA,
                                            const float* __restrict__ Wg,
                                            float* __restrict__ sWhi,
                                            float* __restrict__ sWlo,
                                            float* dstS,
                                            float* __restrict__ dstG,
                                            const float* __restrict__ bias,
                                            bool relu)
{
    const int tid = threadIdx.x;
    const int lane = tid & 31, w = tid >> 5;
    const int g = lane >> 2, ct = lane & 3;
    const int r0 = (w & 3) * 32;
    const int n0 = (w >> 2) * 64;

    float acc[2][8][4];
#pragma unroll
    for (int mt = 0; mt < 2; mt++)
#pragma unroll
        for (int nt = 0; nt < 8; nt++)
#pragma unroll
            for (int i = 0; i < 4; i++) acc[mt][nt][i] = 0.0f;

    for (int kc = 0; kc < 128; kc += 16) {
        __syncthreads();
#pragma unroll
        for (int e = tid; e < 128*16; e += 256) {
            int nn = e >> 4, k = e & 15;
            float wv = Wg[nn*128 + kc + k];
            unsigned hb = tf32b(wv);
            float hf = __uint_as_float(hb);
            sWhi[nn*WKS + k] = hf;
            sWlo[nn*WKS + k] = __uint_as_float(tf32b(wv - hf));
        }
        __syncthreads();
#pragma unroll
        for (int k0 = 0; k0 < 16; k0 += 8) {
            unsigned ahi[2][4], alo[2][4];
#pragma unroll
            for (int mt = 0; mt < 2; mt++) {
                int rb = r0 + mt*16;
                float a0 = sA[(rb+g  )*SAS + kc+k0+ct  ];
                float a1 = sA[(rb+g+8)*SAS + kc+k0+ct  ];
                float a2 = sA[(rb+g  )*SAS + kc+k0+ct+4];
                float a3 = sA[(rb+g+8)*SAS + kc+k0+ct+4];
                ahi[mt][0] = tf32b(a0); alo[mt][0] = tf32b(a0 - __uint_as_float(ahi[mt][0]));
                ahi[mt][1] = tf32b(a1); alo[mt][1] = tf32b(a1 - __uint_as_float(ahi[mt][1]));
                ahi[mt][2] = tf32b(a2); alo[mt][2] = tf32b(a2 - __uint_as_float(ahi[mt][2]));
                ahi[mt][3] = tf32b(a3); alo[mt][3] = tf32b(a3 - __uint_as_float(ahi[mt][3]));
            }
#pragma unroll
            for (int nt = 0; nt < 8; nt++) {
                int nb = (n0 + nt*8 + g)*WKS + k0 + ct;
                unsigned bh0 = __float_as_uint(sWhi[nb]);
                unsigned bh1 = __float_as_uint(sWhi[nb+4]);
                unsigned bl0 = __float_as_uint(sWlo[nb]);
                unsigned bl1 = __float_as_uint(sWlo[nb+4]);
#pragma unroll
                for (int mt = 0; mt < 2; mt++) {
                    mma_tf32(acc[mt][nt], alo[mt][0],alo[mt][1],alo[mt][2],alo[mt][3], bh0, bh1);
                    mma_tf32(acc[mt][nt], ahi[mt][0],ahi[mt][1],ahi[mt][2],ahi[mt][3], bl0, bl1);
                    mma_tf32(acc[mt][nt], ahi[mt][0],ahi[mt][1],ahi[mt][2],ahi[mt][3], bh0, bh1);
                }
            }
        }
    }
    // epilogue
#pragma unroll
    for (int mt = 0; mt < 2; mt++) {
#pragma unroll
        for (int nt = 0; nt < 8; nt++) {
            int ra = r0 + mt*16 + g;
            int ca = n0 + nt*8 + 2*ct;
            float bv0 = bias ? bias[ca]   : 0.0f;
            float bv1 = bias ? bias[ca+1] : 0.0f;
            float v0 = acc[mt][nt][0] + bv0;
            float v1 = acc[mt][nt][1] + bv1;
            float v2 = acc[mt][nt][2] + bv0;
            float v3 = acc[mt][nt][3] + bv1;
            if (relu) { v0=fmaxf(v0,0.f); v1=fmaxf(v1,0.f); v2=fmaxf(v2,0.f); v3=fmaxf(v3,0.f); }
            if (dstS) {
                *reinterpret_cast<float2*>(&dstS[ra*SAS + ca])     = make_float2(v0, v1);
                *reinterpret_cast<float2*>(&dstS[(ra+8)*SAS + ca]) = make_float2(v2, v3);
            } else {
                *reinterpret_cast<float2*>(&dstG[(size_t)ra*128 + ca])     = make_float2(v0, v1);
                *reinterpret_cast<float2*>(&dstG[(size_t)(ra+8)*128 + ca]) = make_float2(v2, v3);
            }
        }
    }
}

// ---------------- QKV projections ----------------
#define QKV_SMEM ((128*SAS + 2*128*WKS) * 4)
__global__ __launch_bounds__(256, 1) void qkv_kernel(const float* __restrict__ feat,
                                                     const float* __restrict__ Wq,
                                                     const float* __restrict__ Wk,
                                                     const float* __restrict__ Wv)
{
    extern __shared__ float sm[];
    float* sA   = sm;                  // 128 x SAS
    float* sWhi = sA + 128*SAS;        // 128 x WKS
    float* sWlo = sWhi + 128*WKS;

    size_t row0 = (size_t)blockIdx.x * 128;
    for (int e = threadIdx.x; e < 128*128; e += 256) {
        int r = e >> 7, c = e & 127;
        sA[r*SAS + c] = feat[(row0 + r)*128 + c];
    }
    gemm_tf32x3(sA, Wq, sWhi, sWlo, nullptr, g_q + row0*128, nullptr, false);
    gemm_tf32x3(sA, Wk, sWhi, sWlo, nullptr, g_k + row0*128, nullptr, false);
    gemm_tf32x3(sA, Wv, sWhi, sWlo, nullptr, g_v + row0*128, nullptr, false);
}

// ---------------- fused main kernel ----------------
// smem bytes: 3*128*132*4 + 2*128*20*4 + 8*128*4 + 3*128*4 + 24*4 + 128*4 = 229472
#define MAIN_SMEM (3*128*SAS*4 + 2*128*WKS*4 + 8*128*4 + 3*128*4 + 24*4 + 128*4)

__global__ __launch_bounds__(256, 1) void main_kernel(const float* __restrict__ xyz,
                                                      const float* __restrict__ pW2,
                                                      const float* __restrict__ pb2,
                                                      const float* __restrict__ aW2,
                                                      const float* __restrict__ ab2,
                                                      const float* __restrict__ Wout,
                                                      float* __restrict__ out)
{
    extern __shared__ float sm[];
    float* sA    = sm;                  // 128 x SAS : hidden / t / logits
    float* sB    = sA + 128*SAS;        // 128 x SAS : h
    float* sP    = sB + 128*SAS;        // 128 x SAS : pos -> v+pos
    float* sWhi  = sP + 128*SAS;        // 128 x WKS
    float* sWlo  = sWhi + 128*WKS;
    float* sOut  = sWlo + 128*WKS;      // 8 x 128
    float* sNx   = sOut + 1024;         // 128
    float* sNy   = sNx + 128;
    float* sNz   = sNy + 128;
    float* sQxyz = sNz + 128;           // 24
    int*   sIdx  = (int*)(sQxyz + 24);  // 128

    const int tid = threadIdx.x;
    const int g0 = blockIdx.x * 8;
    const int b  = g0 >> 13;
    const int n0 = g0 & (NN - 1);
    const float* xb = xyz + (size_t)b * NN * 3;

    if (tid < 128) sIdx[tid] = g_idx[(size_t)g0 * KNB + tid];
    if (tid < 24)  sQxyz[tid] = xb[(size_t)n0 * 3 + tid];
    __syncthreads();
    if (tid < 128) {
        int j = sIdx[tid];
        sNx[tid] = xb[j*3+0]; sNy[tid] = xb[j*3+1]; sNz[tid] = xb[j*3+2];
    }
    __syncthreads();

    // pos hidden = relu(rel @ pW1f^T + pb1f) -> sA (fp32)
    {
        int o = tid & 127;
        float w0 = g_pW1f[o*3+0], w1 = g_pW1f[o*3+1], w2 = g_pW1f[o*3+2], bb = g_pb1f[o];
        for (int r = tid >> 7; r < 128; r += 2) {
            int qi = r >> 4;
            float rx = sNx[r] - sQxyz[qi*3+0];
            float ry = sNy[r] - sQxyz[qi*3+1];
            float rz = sNz[r] - sQxyz[qi*3+2];
            float h = fmaf(rx, w0, fmaf(ry, w1, fmaf(rz, w2, bb)));
            sA[r*SAS + o] = fmaxf(h, 0.0f);
        }
    }
    // pos = hidden @ pW2^T + pb2 -> sP   (gemm's internal sync orders sA writes)
    gemm_tf32x3(sA, pW2, sWhi, sWlo, sP, nullptr, pb2, false);
    __syncthreads();

    // t = q - k + pos -> sA ; vp = v + pos -> sP
    {
        int o = tid & 127;
        for (int r = tid >> 7; r < 128; r += 2) {
            int qi = r >> 4;
            int j = sIdx[r];
            size_t row = ((size_t)b * NN + j) * 128 + o;
            float p = sP[r*SAS + o];
            float qv = g_q[((size_t)g0 + qi) * 128 + o];
            sA[r*SAS + o] = qv - g_k[row] + p;
            sP[r*SAS + o] = g_v[row] + p;
        }
    }
    // h = relu(t @ aW1f^T + ab1f) -> sB ; logits = h @ aW2^T + ab2 -> sA
    gemm_tf32x3(sA, g_aW1f, sWhi, sWlo, sB, nullptr, g_ab1f, true);
    gemm_tf32x3(sB, aW2,    sWhi, sWlo, sA, nullptr, ab2,    false);
    __syncthreads();

    // per-channel softmax over K=16 neighbors; weighted sum of (v+pos)
    for (int it = tid; it < 8*128; it += 256) {
        int qi = it >> 7, o = it & 127;
        int rbase = qi * 16;
        float m = -3.4e38f;
#pragma unroll
        for (int kk = 0; kk < 16; kk++) m = fmaxf(m, sA[(rbase+kk)*SAS + o]);
        float s = 0.0f, acc = 0.0f;
#pragma unroll
        for (int kk = 0; kk < 16; kk++) {
            float e = __expf(sA[(rbase+kk)*SAS + o] - m);
            s += e;
            acc = fmaf(e, sP[(rbase+kk)*SAS + o], acc);
        }
        sOut[qi*128 + o] = acc / s;
    }

    // final: out = sOut @ Wout^T (8x128 rows), Wout staged via sWhi region [128][17]
    float facc[4] = {0.f, 0.f, 0.f, 0.f};
    float* sWs = sWhi;
    for (int kc = 0; kc < 128; kc += 16) {
        __syncthreads();
#pragma unroll
        for (int e = tid; e < 128*16; e += 256) {
            int o = e >> 4, k = e & 15;
            sWs[o*17 + k] = Wout[o*128 + kc + k];
        }
        __syncthreads();
#pragma unroll
        for (int k = 0; k < 16; k++) {
#pragma unroll
            for (int u = 0; u < 4; u++) {
                int it = tid + u*256;
                int qi = it >> 7, o = it & 127;
                facc[u] = fmaf(sOut[qi*128 + kc + k], sWs[o*17 + k], facc[u]);
            }
        }
    }
#pragma unroll
    for (int u = 0; u < 4; u++) {
        int it = tid + u*256;
        int qi = it >> 7, o = it & 127;
        out[((size_t)g0 + qi) * 128 + o] = facc[u];
    }
}

// ---------------- launch ----------------
extern "C" void kernel_launch(void* const* d_in, const int* in_sizes, int n_in,
                              void* d_out, int out_size)
{
    const float* xyz   = (const float*)d_in[0];
    const float* feat  = (const float*)d_in[1];
    const float* Wq    = (const float*)d_in[2];
    const float* Wk    = (const float*)d_in[3];
    const float* Wv    = (const float*)d_in[4];
    const float* pW1   = (const float*)d_in[5];
    const float* pb1   = (const float*)d_in[6];
    const float* pg    = (const float*)d_in[7];
    const float* pbeta = (const float*)d_in[8];
    const float* pmean = (const float*)d_in[9];
    const float* pvar  = (const float*)d_in[10];
    const float* pW2   = (const float*)d_in[11];
    const float* pb2   = (const float*)d_in[12];
    const float* aW1   = (const float*)d_in[13];
    const float* ab1   = (const float*)d_in[14];
    const float* ag    = (const float*)d_in[15];
    const float* abeta = (const float*)d_in[16];
    const float* amean = (const float*)d_in[17];
    const float* avar  = (const float*)d_in[18];
    const float* aW2   = (const float*)d_in[19];
    const float* ab2   = (const float*)d_in[20];
    const float* Wout  = (const float*)d_in[21];
    float* out = (float*)d_out;

    cudaFuncSetAttribute((const void*)knn_kernel,
                         cudaFuncAttributeMaxDynamicSharedMemorySize, KNN_SMEM);
    cudaFuncSetAttribute((const void*)qkv_kernel,
                         cudaFuncAttributeMaxDynamicSharedMemorySize, QKV_SMEM);
    cudaFuncSetAttribute((const void*)main_kernel,
                         cudaFuncAttributeMaxDynamicSharedMemorySize, MAIN_SMEM);

    fold_kernel<<<1, 128>>>(pW1, pb1, pg, pbeta, pmean, pvar,
                            aW1, ab1, ag, abeta, amean, avar);
    knn_kernel<<<(BB*NN)/128, 256, KNN_SMEM>>>(xyz);
    qkv_kernel<<<(BB*NN)/128, 256, QKV_SMEM>>>(feat, Wq, Wk, Wv);
    main_kernel<<<(BB*NN)/8, 256, MAIN_SMEM>>>(xyz, pW2, pb2, aW2, ab2, Wout, out);
}

// round 4
// speedup vs baseline: 1.7112x; 1.4157x over previous
#include <cuda_runtime.h>
#include <cuda_bf16.h>
#include <cstdint>
#include <math.h>

typedef unsigned int u32;

#define BB 2
#define NN 8192
#define CC 128
#define KNB 16
#define EPSF 1e-5f

// bf16 plane row stride: 136 elems = 272 bytes = 17 x 16B banks (ldmatrix conflict-free)
#define BSTR 272
#define PLANE 34816   // 128 * 272 bytes, one bf16 plane
// smem byte offsets (main kernel)
#define OFF_XHI 0
#define OFF_XLO 34816
#define OFF_WHI 69632
#define OFF_WLO 104448
#define OFF_VP  139264
#define OFF_Q   206848
#define OFF_OUT 210944
#define OFF_NX  215040
#define OFF_NY  215552
#define OFF_NZ  216064
#define OFF_QXYZ 216576
#define OFF_IDX 216672
#define MAIN_SMEM 217184
#define QKV_SMEM 139264
#define KNN_SMEM 49152

// ---------------- device scratch ----------------
__device__ float g_q[BB*NN*CC];
__device__ float g_k[BB*NN*CC];
__device__ float g_v[BB*NN*CC];
__device__ int   g_idx[BB*NN*KNB];
__device__ float g_pW1f[CC*3];
__device__ float g_pb1f[CC];
__device__ float g_aW1f[CC*CC];
__device__ float g_ab1f[CC];

// ---------------- asm helpers ----------------
__device__ __forceinline__ u32 cvta_s(const void* p) {
    return (u32)__cvta_generic_to_shared(p);
}
__device__ __forceinline__ void ldsm4(u32 addr, u32 r[4]) {
    asm volatile("ldmatrix.sync.aligned.m8n8.x4.shared.b16 {%0,%1,%2,%3},[%4];"
                 : "=r"(r[0]), "=r"(r[1]), "=r"(r[2]), "=r"(r[3]) : "r"(addr));
}
__device__ __forceinline__ void mma_bf16(float c[4], const u32 a[4],
                                         u32 b0, u32 b1) {
    asm volatile("mma.sync.aligned.m16n8k16.row.col.f32.bf16.bf16.f32 "
                 "{%0,%1,%2,%3},{%4,%5,%6,%7},{%8,%9},{%0,%1,%2,%3};"
                 : "+f"(c[0]), "+f"(c[1]), "+f"(c[2]), "+f"(c[3])
                 : "r"(a[0]), "r"(a[1]), "r"(a[2]), "r"(a[3]), "r"(b0), "r"(b1));
}
// pack {lo half = x, hi half = y} as bf16x2
__device__ __forceinline__ u32 packbf(float x, float y) {
    u32 r; asm("cvt.rn.bf16x2.f32 %0, %1, %2;" : "=r"(r) : "f"(y), "f"(x)); return r;
}
__device__ __forceinline__ float bhi(float v) {
    return __bfloat162float(__float2bfloat16(v));
}
// write (x,y) split into hi/lo bf16 planes at byte offset
__device__ __forceinline__ void split_store(char* hiP, char* loP, int off, float x, float y) {
    float hx = bhi(x), hy = bhi(y);
    *(u32*)(hiP + off) = packbf(hx, hy);
    *(u32*)(loP + off) = packbf(x - hx, y - hy);
}
__device__ __forceinline__ float redmax(float v) {
    v = fmaxf(v, __shfl_xor_sync(0xffffffffu, v, 4));
    v = fmaxf(v, __shfl_xor_sync(0xffffffffu, v, 8));
    v = fmaxf(v, __shfl_xor_sync(0xffffffffu, v, 16));
    return v;
}
__device__ __forceinline__ float redsum(float v) {
    v += __shfl_xor_sync(0xffffffffu, v, 4);
    v += __shfl_xor_sync(0xffffffffu, v, 8);
    v += __shfl_xor_sync(0xffffffffu, v, 16);
    return v;
}

// stage fp32 weight [128][128] -> hi/lo bf16 planes (all 256 threads)
__device__ __forceinline__ void stage_weight(char* sm, const float* __restrict__ Wg) {
    char* hiP = sm + OFF_WHI;
    char* loP = sm + OFF_WLO;
    const int tid = threadIdx.x;
#pragma unroll
    for (int e = tid; e < 8192; e += 256) {
        int n = e >> 6, kp = e & 63;
        float2 wv = *(const float2*)&Wg[n*128 + 2*kp];
        split_store(hiP, loP, n*BSTR + kp*4, wv.x, wv.y);
    }
}

// 128x128x128 GEMM: acc[r][o] = sum_i X[r][i]*W[o][i], X/W split bf16 planes.
// 8 warps: rows 32*(w&3), cols 64*(w>>2). Caller must sync before/after.
__device__ __forceinline__ void mma_gemm(char* sm, float acc[2][8][4]) {
    const int lane = threadIdx.x & 31, w = threadIdx.x >> 5;
    const int r0 = (w & 3) * 32, n0 = (w >> 2) * 64;
    u32 xb = cvta_s(sm + OFF_XHI);
    u32 wb = cvta_s(sm + OFF_WHI);
    const u32 aoff = (u32)(r0 + (lane & 15)) * BSTR + (lane >> 4) * 16;
    const u32 boff = (u32)(n0 + ((lane & 16) >> 1) + (lane & 7)) * BSTR
                   + ((lane >> 3) & 1) * 16;
#pragma unroll
    for (int mt = 0; mt < 2; mt++)
#pragma unroll
        for (int nt = 0; nt < 8; nt++)
#pragma unroll
            for (int i = 0; i < 4; i++) acc[mt][nt][i] = 0.0f;

#pragma unroll 2
    for (int kc = 0; kc < 128; kc += 16) {
        u32 ah0[4], ah1[4], al0[4], al1[4];
        u32 bhm[4][4], blm[4][4];
        ldsm4(xb + aoff + kc*2,                   ah0);
        ldsm4(xb + aoff + 16*BSTR + kc*2,         ah1);
        ldsm4(xb + PLANE + aoff + kc*2,           al0);
        ldsm4(xb + PLANE + aoff + 16*BSTR + kc*2, al1);
#pragma unroll
        for (int p = 0; p < 4; p++) {
            ldsm4(wb + boff + p*16*BSTR + kc*2,         bhm[p]);
            ldsm4(wb + PLANE + boff + p*16*BSTR + kc*2, blm[p]);
        }
#pragma unroll
        for (int p = 0; p < 4; p++) {
#pragma unroll
            for (int h = 0; h < 2; h++) {
                const int nt = 2*p + h;
                const u32 b0h = bhm[p][2*h], b1h = bhm[p][2*h+1];
                const u32 b0l = blm[p][2*h], b1l = blm[p][2*h+1];
                mma_bf16(acc[0][nt], al0, b0h, b1h);
                mma_bf16(acc[0][nt], ah0, b0l, b1l);
                mma_bf16(acc[0][nt], ah0, b0h, b1h);
                mma_bf16(acc[1][nt], al1, b0h, b1h);
                mma_bf16(acc[1][nt], ah1, b0l, b1l);
                mma_bf16(acc[1][nt], ah1, b0h, b1h);
            }
        }
    }
}

// ---------------- fold BN into preceding linears ----------------
__global__ void fold_kernel(const float* __restrict__ pW1, const float* __restrict__ pb1,
                            const float* __restrict__ pg,  const float* __restrict__ pbeta,
                            const float* __restrict__ pmean,const float* __restrict__ pvar,
                            const float* __restrict__ aW1, const float* __restrict__ ab1,
                            const float* __restrict__ ag,  const float* __restrict__ abeta,
                            const float* __restrict__ amean,const float* __restrict__ avar)
{
    int o = threadIdx.x;
    if (o >= CC) return;
    float s = pg[o] * rsqrtf(pvar[o] + EPSF);
    g_pW1f[o*3+0] = pW1[o*3+0] * s;
    g_pW1f[o*3+1] = pW1[o*3+1] * s;
    g_pW1f[o*3+2] = pW1[o*3+2] * s;
    g_pb1f[o] = pb1[o]*s + pbeta[o] - pmean[o]*s;

    float sa = ag[o] * rsqrtf(avar[o] + EPSF);
    for (int i = 0; i < CC; i++) g_aW1f[o*CC+i] = aW1[o*CC+i] * sa;
    g_ab1f[o] = ab1[o]*sa + abeta[o] - amean[o]*sa;
}

// ---------------- KNN: 2 threads per query ----------------
__global__ __launch_bounds__(256, 1) void knn_kernel(const float* __restrict__ xyz)
{
    extern __shared__ float ksm[];
    float* sx = ksm;
    float* sy = sx + 2048;
    float* sz = sy + 2048;
    float* ss = sz + 2048;
    float* sMD = ss + 2048;
    int*   sMI = (int*)(sMD + 2048);

    const int tid = threadIdx.x;
    const int qloc = tid >> 1;
    const int par  = tid & 1;
    const int b = blockIdx.x >> 6;
    const int n = ((blockIdx.x & 63) << 7) + qloc;
    const float* base = xyz + (size_t)b * NN * 3;

    float qx = base[n*3+0], qy = base[n*3+1], qz = base[n*3+2];
    float qs = qx*qx + qy*qy + qz*qz;

    float bd[KNB]; int bi[KNB];
#pragma unroll
    for (int t = 0; t < KNB; t++) { bd[t] = 3.4e38f; bi[t] = 0; }
    float worst = 3.4e38f; int wpos = 0;

    for (int t0 = 0; t0 < NN; t0 += 2048) {
        __syncthreads();
        for (int e = tid; e < 2048; e += 256) {
            int j = t0 + e;
            float x = base[j*3+0], y = base[j*3+1], z = base[j*3+2];
            sx[e] = x; sy[e] = y; sz[e] = z; ss[e] = x*x + y*y + z*z;
        }
        __syncthreads();
#pragma unroll 4
        for (int e = par; e < 2048; e += 2) {
            float d = qs + ss[e] - 2.0f*(qx*sx[e] + qy*sy[e] + qz*sz[e]);
            if (d < worst) {
                int j = t0 + e;
#pragma unroll
                for (int t = 0; t < KNB; t++) if (t == wpos) { bd[t] = d; bi[t] = j; }
                worst = -3.4e38f;
#pragma unroll
                for (int t = 0; t < KNB; t++) if (bd[t] > worst) { worst = bd[t]; wpos = t; }
            }
        }
    }
    __syncthreads();
    if (par == 1) {
#pragma unroll
        for (int t = 0; t < KNB; t++) { sMD[qloc*KNB+t] = bd[t]; sMI[qloc*KNB+t] = bi[t]; }
    }
    __syncthreads();
    if (par == 0) {
#pragma unroll
        for (int t = 0; t < KNB; t++) {
            float d = sMD[qloc*KNB+t];
            if (d < worst) {
                int j = sMI[qloc*KNB+t];
#pragma unroll
                for (int u = 0; u < KNB; u++) if (u == wpos) { bd[u] = d; bi[u] = j; }
                worst = -3.4e38f;
#pragma unroll
                for (int u = 0; u < KNB; u++) if (bd[u] > worst) { worst = bd[u]; wpos = u; }
            }
        }
        int q = b*NN + n;
#pragma unroll
        for (int t = 0; t < KNB; t++) g_idx[q*KNB + t] = bi[t];
    }
}

// ---------------- QKV projections ----------------
__global__ __launch_bounds__(256, 1) void qkv_kernel(const float* __restrict__ feat,
                                                     const float* __restrict__ Wq,
                                                     const float* __restrict__ Wk,
                                                     const float* __restrict__ Wv)
{
    extern __shared__ char sm[];
    char* xhiP = sm + OFF_XHI;
    char* xloP = sm + OFF_XLO;
    const int tid = threadIdx.x;
    const int lane = tid & 31, w = tid >> 5;
    const int r0 = (w & 3) * 32, n0 = (w >> 2) * 64;
    const int g = lane >> 2, ct = lane & 3;
    size_t row0 = (size_t)blockIdx.x * 128;

    // stage feat split
#pragma unroll
    for (int e = tid; e < 8192; e += 256) {
        int r = e >> 6, kp = e & 63;
        float2 f = *(const float2*)&feat[(row0 + r)*128 + 2*kp];
        split_store(xhiP, xloP, r*BSTR + kp*4, f.x, f.y);
    }

    const float* Ws[3] = {Wq, Wk, Wv};
    float* Gs[3] = {g_q, g_k, g_v};
#pragma unroll 1
    for (int m = 0; m < 3; m++) {
        __syncthreads();
        stage_weight(sm, Ws[m]);
        __syncthreads();
        float acc[2][8][4];
        mma_gemm(sm, acc);
        float* dst = Gs[m] + row0*128;
#pragma unroll
        for (int mt = 0; mt < 2; mt++)
#pragma unroll
            for (int nt = 0; nt < 8; nt++) {
                int ra = r0 + mt*16 + g;
                int ca = n0 + nt*8 + 2*ct;
                *(float2*)&dst[(size_t)ra*128 + ca]     = make_float2(acc[mt][nt][0], acc[mt][nt][1]);
                *(float2*)&dst[(size_t)(ra+8)*128 + ca] = make_float2(acc[mt][nt][2], acc[mt][nt][3]);
            }
    }
}

// ---------------- fused main kernel: 8 queries (128 pair-rows) per block ----------------
__global__ __launch_bounds__(256, 1) void main_kernel(const float* __restrict__ xyz,
                                                      const float* __restrict__ pW2,
                                                      const float* __restrict__ pb2,
                                                      const float* __restrict__ aW2,
                                                      const float* __restrict__ ab2,
                                                      const float* __restrict__ Wout,
                                                      float* __restrict__ out)
{
    extern __shared__ char sm[];
    char* xhiP = sm + OFF_XHI;
    char* xloP = sm + OFF_XLO;
    float* sVp  = (float*)(sm + OFF_VP);    // [128][132]
    float* sQ   = (float*)(sm + OFF_Q);     // [8][128]
    float* sOut = (float*)(sm + OFF_OUT);   // [8][128]
    float* sNx  = (float*)(sm + OFF_NX);
    float* sNy  = (float*)(sm + OFF_NY);
    float* sNz  = (float*)(sm + OFF_NZ);
    float* sQxyz= (float*)(sm + OFF_QXYZ);
    int*   sIdx = (int*)(sm + OFF_IDX);

    const int tid = threadIdx.x;
    const int lane = tid & 31, w = tid >> 5;
    const int r0 = (w & 3) * 32, n0 = (w >> 2) * 64;
    const int g = lane >> 2, ct = lane & 3;
    const int g0 = blockIdx.x * 8;
    const int b  = g0 >> 13;
    const int n0q = g0 & (NN - 1);
    const size_t bN = (size_t)b * NN;
    const float* xb = xyz + bN * 3;

    if (tid < 128) sIdx[tid] = g_idx[(size_t)g0 * KNB + tid];
    if (tid < 24)  sQxyz[tid] = xb[(size_t)n0q * 3 + tid];
    for (int e = tid; e < 1024; e += 256) sQ[e] = g_q[(size_t)g0 * 128 + e];
    __syncthreads();
    if (tid < 128) {
        int j = sIdx[tid];
        sNx[tid] = xb[j*3+0]; sNy[tid] = xb[j*3+1]; sNz[tid] = xb[j*3+2];
    }
    // stage pW2 while xyz settle
    stage_weight(sm, pW2);

    // pos hidden = relu(rel @ pW1f^T + pb1f) -> split planes
    __syncthreads();
#pragma unroll
    for (int e = tid; e < 8192; e += 256) {
        int r = e >> 6, kp = e & 63;
        int o0 = 2*kp, o1 = 2*kp + 1;
        int qi = r >> 4;
        float rx = sNx[r] - sQxyz[qi*3+0];
        float ry = sNy[r] - sQxyz[qi*3+1];
        float rz = sNz[r] - sQxyz[qi*3+2];
        float h0 = fmaf(rx, g_pW1f[o0*3+0], fmaf(ry, g_pW1f[o0*3+1], fmaf(rz, g_pW1f[o0*3+2], g_pb1f[o0])));
        float h1 = fmaf(rx, g_pW1f[o1*3+0], fmaf(ry, g_pW1f[o1*3+1], fmaf(rz, g_pW1f[o1*3+2], g_pb1f[o1])));
        split_store(xhiP, xloP, r*BSTR + kp*4, fmaxf(h0, 0.f), fmaxf(h1, 0.f));
    }
    __syncthreads();

    // GEMM1: pos = hidden @ pW2^T + pb2 ; epilogue builds t (split) and vp (sVp)
    {
        float acc[2][8][4];
        mma_gemm(sm, acc);
        __syncthreads();   // everyone done reading planes
#pragma unroll
        for (int mt = 0; mt < 2; mt++) {
            int qi = (r0 >> 4) + mt;
#pragma unroll
            for (int nt = 0; nt < 8; nt++) {
                int ca = n0 + nt*8 + 2*ct;
                int ra0 = r0 + mt*16 + g, ra1 = ra0 + 8;
                float pb0 = __ldg(&pb2[ca]), pb1 = __ldg(&pb2[ca+1]);
                float p00 = acc[mt][nt][0] + pb0, p01 = acc[mt][nt][1] + pb1;
                float p10 = acc[mt][nt][2] + pb0, p11 = acc[mt][nt][3] + pb1;
                int j0 = sIdx[ra0], j1 = sIdx[ra1];
                float2 qv = *(const float2*)&sQ[qi*128 + ca];
                float2 k0 = *(const float2*)&g_k[(bN + j0)*128 + ca];
                float2 v0 = *(const float2*)&g_v[(bN + j0)*128 + ca];
                float2 k1 = *(const float2*)&g_k[(bN + j1)*128 + ca];
                float2 v1 = *(const float2*)&g_v[(bN + j1)*128 + ca];
                *(float2*)&sVp[ra0*132 + ca] = make_float2(v0.x + p00, v0.y + p01);
                *(float2*)&sVp[ra1*132 + ca] = make_float2(v1.x + p10, v1.y + p11);
                split_store(xhiP, xloP, ra0*BSTR + ca*2, qv.x - k0.x + p00, qv.y - k0.y + p01);
                split_store(xhiP, xloP, ra1*BSTR + ca*2, qv.x - k1.x + p10, qv.y - k1.y + p11);
            }
        }
        stage_weight(sm, g_aW1f);
        __syncthreads();
    }

    // GEMM2: h = relu(t @ aW1f^T + ab1f)
    {
        float acc[2][8][4];
        mma_gemm(sm, acc);
        __syncthreads();
#pragma unroll
        for (int mt = 0; mt < 2; mt++)
#pragma unroll
            for (int nt = 0; nt < 8; nt++) {
                int ca = n0 + nt*8 + 2*ct;
                int ra0 = r0 + mt*16 + g, ra1 = ra0 + 8;
                float b0 = __ldg(&g_ab1f[ca]), b1 = __ldg(&g_ab1f[ca+1]);
                split_store(xhiP, xloP, ra0*BSTR + ca*2,
                            fmaxf(acc[mt][nt][0] + b0, 0.f), fmaxf(acc[mt][nt][1] + b1, 0.f));
                split_store(xhiP, xloP, ra1*BSTR + ca*2,
                            fmaxf(acc[mt][nt][2] + b0, 0.f), fmaxf(acc[mt][nt][3] + b1, 0.f));
            }
        stage_weight(sm, aW2);
        __syncthreads();
    }

    // GEMM3: logits = h @ aW2^T + ab2 ; softmax over K=16 in registers; weighted vp sum
    {
        float acc[2][8][4];
        mma_gemm(sm, acc);
#pragma unroll
        for (int mt = 0; mt < 2; mt++) {
            int qi = (r0 >> 4) + mt;
#pragma unroll
            for (int nt = 0; nt < 8; nt++) {
                int ca = n0 + nt*8 + 2*ct;
                int ra0 = r0 + mt*16 + g, ra1 = ra0 + 8;
                float b0 = __ldg(&ab2[ca]), b1 = __ldg(&ab2[ca+1]);
                float l00 = acc[mt][nt][0] + b0, l01 = acc[mt][nt][1] + b1;
                float l10 = acc[mt][nt][2] + b0, l11 = acc[mt][nt][3] + b1;
                float m0 = redmax(fmaxf(l00, l10));
                float m1 = redmax(fmaxf(l01, l11));
                float e00 = __expf(l00 - m0), e10 = __expf(l10 - m0);
                float e01 = __expf(l01 - m1), e11 = __expf(l11 - m1);
                float s0 = redsum(e00 + e10);
                float s1 = redsum(e01 + e11);
                float2 vpa = *(const float2*)&sVp[ra0*132 + ca];
                float2 vpb = *(const float2*)&sVp[ra1*132 + ca];
                float w0 = redsum(fmaf(e00, vpa.x, e10 * vpb.x));
                float w1 = redsum(fmaf(e01, vpa.y, e11 * vpb.y));
                if (g == 0)
                    *(float2*)&sOut[qi*128 + ca] = make_float2(w0 / s0, w1 / s1);
            }
        }
        __syncthreads();
    }

    // final: out = sOut @ Wout^T (8x128 rows). Wout chunks staged in WHI area (fp32).
    {
        float* sWs = (float*)(sm + OFF_WHI);  // [128][17]
        float facc[4] = {0.f, 0.f, 0.f, 0.f};
        for (int kc = 0; kc < 128; kc += 16) {
            __syncthreads();
#pragma unroll
            for (int e = tid; e < 2048; e += 256) {
                int o = e >> 4, k = e & 15;
                sWs[o*17 + k] = Wout[o*128 + kc + k];
            }
            __syncthreads();
#pragma unroll
            for (int k = 0; k < 16; k++) {
#pragma unroll
                for (int u = 0; u < 4; u++) {
                    int it = tid + u*256;
                    int qi = it >> 7, o = it & 127;
                    facc[u] = fmaf(sOut[qi*128 + kc + k], sWs[o*17 + k], facc[u]);
                }
            }
        }
#pragma unroll
        for (int u = 0; u < 4; u++) {
            int it = tid + u*256;
            int qi = it >> 7, o = it & 127;
            out[((size_t)g0 + qi) * 128 + o] = facc[u];
        }
    }
}

// ---------------- launch ----------------
extern "C" void kernel_launch(void* const* d_in, const int* in_sizes, int n_in,
                              void* d_out, int out_size)
{
    const float* xyz   = (const float*)d_in[0];
    const float* feat  = (const float*)d_in[1];
    const float* Wq    = (const float*)d_in[2];
    const float* Wk    = (const float*)d_in[3];
    const float* Wv    = (const float*)d_in[4];
    const float* pW1   = (const float*)d_in[5];
    const float* pb1   = (const float*)d_in[6];
    const float* pg    = (const float*)d_in[7];
    const float* pbeta = (const float*)d_in[8];
    const float* pmean = (const float*)d_in[9];
    const float* pvar  = (const float*)d_in[10];
    const float* pW2   = (const float*)d_in[11];
    const float* pb2   = (const float*)d_in[12];
    const float* aW1   = (const float*)d_in[13];
    const float* ab1   = (const float*)d_in[14];
    const float* ag    = (const float*)d_in[15];
    const float* abeta = (const float*)d_in[16];
    const float* amean = (const float*)d_in[17];
    const float* avar  = (const float*)d_in[18];
    const float* aW2   = (const float*)d_in[19];
    const float* ab2   = (const float*)d_in[20];
    const float* Wout  = (const float*)d_in[21];
    float* out = (float*)d_out;

    cudaFuncSetAttribute((const void*)knn_kernel,
                         cudaFuncAttributeMaxDynamicSharedMemorySize, KNN_SMEM);
    cudaFuncSetAttribute((const void*)qkv_kernel,
                         cudaFuncAttributeMaxDynamicSharedMemorySize, QKV_SMEM);
    cudaFuncSetAttribute((const void*)main_kernel,
                         cudaFuncAttributeMaxDynamicSharedMemorySize, MAIN_SMEM);

    fold_kernel<<<1, 128>>>(pW1, pb1, pg, pbeta, pmean, pvar,
                            aW1, ab1, ag, abeta, amean, avar);
    knn_kernel<<<(BB*NN)/128, 256, KNN_SMEM>>>(xyz);
    qkv_kernel<<<(BB*NN)/128, 256, QKV_SMEM>>>(feat, Wq, Wk, Wv);
    main_kernel<<<(BB*NN)/8, 256, MAIN_SMEM>>>(xyz, pW2, pb2, aW2, ab2, Wout, out);
}

// round 5
// speedup vs baseline: 1.8754x; 1.0960x over previous
#include <cuda_runtime.h>
#include <cuda_bf16.h>
#include <cstdint>
#include <math.h>

typedef unsigned int u32;

#define BB 2
#define NN 8192
#define CC 128
#define KNB 16
#define EPSF 1e-5f

// bf16 plane row stride: 136 elems = 272 bytes = 17 x 16B banks (ldmatrix conflict-free)
#define BSTR 272
#define PLANE 34816   // 128 * 272 bytes, one bf16 plane
// smem byte offsets (main kernel)
#define OFF_XHI 0
#define OFF_XLO 34816
#define OFF_WHI 69632
#define OFF_WLO 104448
#define OFF_VP  139264
#define OFF_Q   206848
#define OFF_OUT 210944
#define OFF_NX  215040
#define OFF_NY  215552
#define OFF_NZ  216064
#define OFF_QXYZ 216576
#define OFF_IDX 216672
#define MAIN_SMEM 217184
#define QKV_SMEM 139264
#define KNN_SMEM 57344

// ---------------- device scratch ----------------
__device__ float g_q[BB*NN*CC];
__device__ float g_k[BB*NN*CC];
__device__ float g_v[BB*NN*CC];
__device__ int   g_idx[BB*NN*KNB];
__device__ float g_pW1f[CC*3];
__device__ float g_pb1f[CC];
__device__ float g_aW1f[CC*CC];
__device__ float g_ab1f[CC];

// ---------------- asm helpers ----------------
__device__ __forceinline__ u32 cvta_s(const void* p) {
    return (u32)__cvta_generic_to_shared(p);
}
__device__ __forceinline__ void ldsm4(u32 addr, u32 r[4]) {
    asm volatile("ldmatrix.sync.aligned.m8n8.x4.shared.b16 {%0,%1,%2,%3},[%4];"
                 : "=r"(r[0]), "=r"(r[1]), "=r"(r[2]), "=r"(r[3]) : "r"(addr));
}
__device__ __forceinline__ void mma_bf16(float c[4], const u32 a[4],
                                         u32 b0, u32 b1) {
    asm volatile("mma.sync.aligned.m16n8k16.row.col.f32.bf16.bf16.f32 "
                 "{%0,%1,%2,%3},{%4,%5,%6,%7},{%8,%9},{%0,%1,%2,%3};"
                 : "+f"(c[0]), "+f"(c[1]), "+f"(c[2]), "+f"(c[3])
                 : "r"(a[0]), "r"(a[1]), "r"(a[2]), "r"(a[3]), "r"(b0), "r"(b1));
}
__device__ __forceinline__ u32 packbf(float x, float y) {
    u32 r; asm("cvt.rn.bf16x2.f32 %0, %1, %2;" : "=r"(r) : "f"(y), "f"(x)); return r;
}
__device__ __forceinline__ float bhi(float v) {
    return __bfloat162float(__float2bfloat16(v));
}
__device__ __forceinline__ void split_store(char* hiP, char* loP, int off, float x, float y) {
    float hx = bhi(x), hy = bhi(y);
    *(u32*)(hiP + off) = packbf(hx, hy);
    *(u32*)(loP + off) = packbf(x - hx, y - hy);
}
__device__ __forceinline__ float redmax(float v) {
    v = fmaxf(v, __shfl_xor_sync(0xffffffffu, v, 4));
    v = fmaxf(v, __shfl_xor_sync(0xffffffffu, v, 8));
    v = fmaxf(v, __shfl_xor_sync(0xffffffffu, v, 16));
    return v;
}
__device__ __forceinline__ float redsum(float v) {
    v += __shfl_xor_sync(0xffffffffu, v, 4);
    v += __shfl_xor_sync(0xffffffffu, v, 8);
    v += __shfl_xor_sync(0xffffffffu, v, 16);
    return v;
}

// stage fp32 weight [128][128] -> hi/lo bf16 planes (NT threads)
template<int NT>
__device__ __forceinline__ void stage_weight(char* sm, const float* __restrict__ Wg) {
    char* hiP = sm + OFF_WHI;
    char* loP = sm + OFF_WLO;
    const int tid = threadIdx.x;
#pragma unroll
    for (int e = tid; e < 8192; e += NT) {
        int n = e >> 6, kp = e & 63;
        float2 wv = *(const float2*)&Wg[n*128 + 2*kp];
        split_store(hiP, loP, n*BSTR + kp*4, wv.x, wv.y);
    }
}

// 128x128x128 GEMM: acc[r][o] = sum_i X[r][i]*W[o][i], X/W split bf16 planes.
// 16 warps: warp w -> rows 16*(w&7) (one 16-row m-tile), cols 64*(w>>3) (8 n-tiles).
// Caller must sync before/after.
__device__ __forceinline__ void mma_gemm(char* sm, float acc[8][4]) {
    const int lane = threadIdx.x & 31, w = threadIdx.x >> 5;
    const int r0 = (w & 7) * 16, n0 = (w >> 3) * 64;
    u32 xb = cvta_s(sm + OFF_XHI);
    u32 wb = cvta_s(sm + OFF_WHI);
    const u32 aoff = (u32)(r0 + (lane & 15)) * BSTR + (lane >> 4) * 16;
    const u32 boff = (u32)(n0 + ((lane & 16) >> 1) + (lane & 7)) * BSTR
                   + ((lane >> 3) & 1) * 16;
#pragma unroll
    for (int nt = 0; nt < 8; nt++)
#pragma unroll
        for (int i = 0; i < 4; i++) acc[nt][i] = 0.0f;

#pragma unroll 2
    for (int kc = 0; kc < 128; kc += 16) {
        u32 ah[4], al[4];
        u32 bhm[4][4], blm[4][4];
        ldsm4(xb + aoff + kc*2,         ah);
        ldsm4(xb + PLANE + aoff + kc*2, al);
#pragma unroll
        for (int p = 0; p < 4; p++) {
            ldsm4(wb + boff + p*16*BSTR + kc*2,         bhm[p]);
            ldsm4(wb + PLANE + boff + p*16*BSTR + kc*2, blm[p]);
        }
#pragma unroll
        for (int p = 0; p < 4; p++) {
#pragma unroll
            for (int h = 0; h < 2; h++) {
                const int nt = 2*p + h;
                const u32 b0h = bhm[p][2*h], b1h = bhm[p][2*h+1];
                const u32 b0l = blm[p][2*h], b1l = blm[p][2*h+1];
                mma_bf16(acc[nt], al, b0h, b1h);
                mma_bf16(acc[nt], ah, b0l, b1l);
                mma_bf16(acc[nt], ah, b0h, b1h);
            }
        }
    }
}

// ---------------- fold BN into preceding linears ----------------
__global__ void fold_kernel(const float* __restrict__ pW1, const float* __restrict__ pb1,
                            const float* __restrict__ pg,  const float* __restrict__ pbeta,
                            const float* __restrict__ pmean,const float* __restrict__ pvar,
                            const float* __restrict__ aW1, const float* __restrict__ ab1,
                            const float* __restrict__ ag,  const float* __restrict__ abeta,
                            const float* __restrict__ amean,const float* __restrict__ avar)
{
    int tid = threadIdx.x;              // 512 threads
    if (tid < CC) {
        int o = tid;
        float s = pg[o] * rsqrtf(pvar[o] + EPSF);
        g_pW1f[o*3+0] = pW1[o*3+0] * s;
        g_pW1f[o*3+1] = pW1[o*3+1] * s;
        g_pW1f[o*3+2] = pW1[o*3+2] * s;
        g_pb1f[o] = pb1[o]*s + pbeta[o] - pmean[o]*s;
        float sa = ag[o] * rsqrtf(avar[o] + EPSF);
        g_ab1f[o] = ab1[o]*sa + abeta[o] - amean[o]*sa;
    }
    for (int e = tid; e < CC*CC; e += 512) {
        int o = e >> 7;
        float sa = ag[o] * rsqrtf(avar[o] + EPSF);
        g_aW1f[e] = aW1[e] * sa;
    }
}

// ---------------- KNN: 4 threads per query ----------------
// 256 blocks x 256 threads; block handles 64 queries; thread scans 2048 candidates.
__global__ __launch_bounds__(256, 1) void knn_kernel(const float* __restrict__ xyz)
{
    extern __shared__ float ksm[];
    float* sx = ksm;            // 2048
    float* sy = sx + 2048;
    float* sz = sy + 2048;
    float* ss = sz + 2048;
    float* sMD = ss + 2048;     // 64*3*16
    int*   sMI = (int*)(sMD + 3072);

    const int tid = threadIdx.x;
    const int qloc = tid >> 2;          // 0..63
    const int par  = tid & 3;
    const int b = blockIdx.x >> 7;
    const int n = ((blockIdx.x & 127) << 6) + qloc;
    const float* base = xyz + (size_t)b * NN * 3;

    float qx = base[n*3+0], qy = base[n*3+1], qz = base[n*3+2];
    float qs = qx*qx + qy*qy + qz*qz;

    float bd[KNB]; int bi[KNB];
#pragma unroll
    for (int t = 0; t < KNB; t++) { bd[t] = 3.4e38f; bi[t] = 0; }
    float worst = 3.4e38f; int wpos = 0;

    for (int t0 = 0; t0 < NN; t0 += 2048) {
        __syncthreads();
        for (int e = tid; e < 2048; e += 256) {
            int j = t0 + e;
            float x = base[j*3+0], y = base[j*3+1], z = base[j*3+2];
            sx[e] = x; sy[e] = y; sz[e] = z; ss[e] = x*x + y*y + z*z;
        }
        __syncthreads();
#pragma unroll 4
        for (int e = par; e < 2048; e += 4) {
            float d = qs + ss[e] - 2.0f*(qx*sx[e] + qy*sy[e] + qz*sz[e]);
            if (d < worst) {
                int j = t0 + e;
#pragma unroll
                for (int t = 0; t < KNB; t++) if (t == wpos) { bd[t] = d; bi[t] = j; }
                worst = -3.4e38f;
#pragma unroll
                for (int t = 0; t < KNB; t++) if (bd[t] > worst) { worst = bd[t]; wpos = t; }
            }
        }
    }
    __syncthreads();
    if (par != 0) {
        int slot = qloc*3 + (par-1);
#pragma unroll
        for (int t = 0; t < KNB; t++) { sMD[slot*KNB+t] = bd[t]; sMI[slot*KNB+t] = bi[t]; }
    }
    __syncthreads();
    if (par == 0) {
#pragma unroll 1
        for (int m = 0; m < 3; m++) {
            int slot = qloc*3 + m;
#pragma unroll
            for (int t = 0; t < KNB; t++) {
                float d = sMD[slot*KNB+t];
                if (d < worst) {
                    int j = sMI[slot*KNB+t];
#pragma unroll
                    for (int u = 0; u < KNB; u++) if (u == wpos) { bd[u] = d; bi[u] = j; }
                    worst = -3.4e38f;
#pragma unroll
                    for (int u = 0; u < KNB; u++) if (bd[u] > worst) { worst = bd[u]; wpos = u; }
                }
            }
        }
        int q = b*NN + n;
#pragma unroll
        for (int t = 0; t < KNB; t++) g_idx[q*KNB + t] = bi[t];
    }
}

// ---------------- QKV projections (512 threads) ----------------
__global__ __launch_bounds__(512, 1) void qkv_kernel(const float* __restrict__ feat,
                                                     const float* __restrict__ Wq,
                                                     const float* __restrict__ Wk,
                                                     const float* __restrict__ Wv)
{
    extern __shared__ char sm[];
    char* xhiP = sm + OFF_XHI;
    char* xloP = sm + OFF_XLO;
    const int tid = threadIdx.x;
    const int lane = tid & 31, w = tid >> 5;
    const int r0 = (w & 7) * 16, n0 = (w >> 3) * 64;
    const int g = lane >> 2, ct = lane & 3;
    size_t row0 = (size_t)blockIdx.x * 128;

#pragma unroll
    for (int e = tid; e < 8192; e += 512) {
        int r = e >> 6, kp = e & 63;
        float2 f = *(const float2*)&feat[(row0 + r)*128 + 2*kp];
        split_store(xhiP, xloP, r*BSTR + kp*4, f.x, f.y);
    }

    const float* Ws[3] = {Wq, Wk, Wv};
    float* Gs[3] = {g_q, g_k, g_v};
#pragma unroll 1
    for (int m = 0; m < 3; m++) {
        __syncthreads();
        stage_weight<512>(sm, Ws[m]);
        __syncthreads();
        float acc[8][4];
        mma_gemm(sm, acc);
        float* dst = Gs[m] + row0*128;
#pragma unroll
        for (int nt = 0; nt < 8; nt++) {
            int ra = r0 + g;
            int ca = n0 + nt*8 + 2*ct;
            *(float2*)&dst[(size_t)ra*128 + ca]     = make_float2(acc[nt][0], acc[nt][1]);
            *(float2*)&dst[(size_t)(ra+8)*128 + ca] = make_float2(acc[nt][2], acc[nt][3]);
        }
    }
}

// ---------------- fused main kernel: 8 queries (128 pair-rows), 512 threads ----------------
__global__ __launch_bounds__(512, 1) void main_kernel(const float* __restrict__ xyz,
                                                      const float* __restrict__ pW2,
                                                      const float* __restrict__ pb2,
                                                      const float* __restrict__ aW2,
                                                      const float* __restrict__ ab2,
                                                      const float* __restrict__ Wout,
                                                      float* __restrict__ out)
{
    extern __shared__ char sm[];
    char* xhiP = sm + OFF_XHI;
    char* xloP = sm + OFF_XLO;
    float* sVp  = (float*)(sm + OFF_VP);    // [128][132]
    float* sQ   = (float*)(sm + OFF_Q);     // [8][128]
    float* sOut = (float*)(sm + OFF_OUT);   // [8][128]
    float* sNx  = (float*)(sm + OFF_NX);
    float* sNy  = (float*)(sm + OFF_NY);
    float* sNz  = (float*)(sm + OFF_NZ);
    float* sQxyz= (float*)(sm + OFF_QXYZ);
    int*   sIdx = (int*)(sm + OFF_IDX);

    const int tid = threadIdx.x;
    const int lane = tid & 31, w = tid >> 5;
    const int r0 = (w & 7) * 16, n0 = (w >> 3) * 64;
    const int g = lane >> 2, ct = lane & 3;
    const int g0 = blockIdx.x * 8;
    const int b  = g0 >> 13;
    const int n0q = g0 & (NN - 1);
    const size_t bN = (size_t)b * NN;
    const float* xb = xyz + bN * 3;
    const int qi = r0 >> 4;                 // warp's query (= w&7)

    if (tid < 128) sIdx[tid] = g_idx[(size_t)g0 * KNB + tid];
    if (tid < 24)  sQxyz[tid] = xb[(size_t)n0q * 3 + tid];
    for (int e = tid; e < 1024; e += 512) sQ[e] = g_q[(size_t)g0 * 128 + e];
    __syncthreads();
    if (tid < 128) {
        int j = sIdx[tid];
        sNx[tid] = xb[j*3+0]; sNy[tid] = xb[j*3+1]; sNz[tid] = xb[j*3+2];
    }
    stage_weight<512>(sm, pW2);

    __syncthreads();
#pragma unroll
    for (int e = tid; e < 8192; e += 512) {
        int r = e >> 6, kp = e & 63;
        int o0 = 2*kp, o1 = 2*kp + 1;
        int qr = r >> 4;
        float rx = sNx[r] - sQxyz[qr*3+0];
        float ry = sNy[r] - sQxyz[qr*3+1];
        float rz = sNz[r] - sQxyz[qr*3+2];
        float h0 = fmaf(rx, g_pW1f[o0*3+0], fmaf(ry, g_pW1f[o0*3+1], fmaf(rz, g_pW1f[o0*3+2], g_pb1f[o0])));
        float h1 = fmaf(rx, g_pW1f[o1*3+0], fmaf(ry, g_pW1f[o1*3+1], fmaf(rz, g_pW1f[o1*3+2], g_pb1f[o1])));
        split_store(xhiP, xloP, r*BSTR + kp*4, fmaxf(h0, 0.f), fmaxf(h1, 0.f));
    }
    __syncthreads();

    // GEMM1: pos = hidden @ pW2^T + pb2 ; epilogue builds t (split) and vp (sVp)
    {
        float acc[8][4];
        mma_gemm(sm, acc);
        __syncthreads();
#pragma unroll
        for (int nt = 0; nt < 8; nt++) {
            int ca = n0 + nt*8 + 2*ct;
            int ra0 = r0 + g, ra1 = ra0 + 8;
            float pb0 = __ldg(&pb2[ca]), pb1 = __ldg(&pb2[ca+1]);
            float p00 = acc[nt][0] + pb0, p01 = acc[nt][1] + pb1;
            float p10 = acc[nt][2] + pb0, p11 = acc[nt][3] + pb1;
            int j0 = sIdx[ra0], j1 = sIdx[ra1];
            float2 qv = *(const float2*)&sQ[qi*128 + ca];
            float2 k0 = *(const float2*)&g_k[(bN + j0)*128 + ca];
            float2 v0 = *(const float2*)&g_v[(bN + j0)*128 + ca];
            float2 k1 = *(const float2*)&g_k[(bN + j1)*128 + ca];
            float2 v1 = *(const float2*)&g_v[(bN + j1)*128 + ca];
            *(float2*)&sVp[ra0*132 + ca] = make_float2(v0.x + p00, v0.y + p01);
            *(float2*)&sVp[ra1*132 + ca] = make_float2(v1.x + p10, v1.y + p11);
            split_store(xhiP, xloP, ra0*BSTR + ca*2, qv.x - k0.x + p00, qv.y - k0.y + p01);
            split_store(xhiP, xloP, ra1*BSTR + ca*2, qv.x - k1.x + p10, qv.y - k1.y + p11);
        }
        stage_weight<512>(sm, g_aW1f);
        __syncthreads();
    }

    // GEMM2: h = relu(t @ aW1f^T + ab1f)
    {
        float acc[8][4];
        mma_gemm(sm, acc);
        __syncthreads();
#pragma unroll
        for (int nt = 0; nt < 8; nt++) {
            int ca = n0 + nt*8 + 2*ct;
            int ra0 = r0 + g, ra1 = ra0 + 8;
            float b0 = __ldg(&g_ab1f[ca]), b1 = __ldg(&g_ab1f[ca+1]);
            split_store(xhiP, xloP, ra0*BSTR + ca*2,
                        fmaxf(acc[nt][0] + b0, 0.f), fmaxf(acc[nt][1] + b1, 0.f));
            split_store(xhiP, xloP, ra1*BSTR + ca*2,
                        fmaxf(acc[nt][2] + b0, 0.f), fmaxf(acc[nt][3] + b1, 0.f));
        }
        stage_weight<512>(sm, aW2);
        __syncthreads();
    }

    // GEMM3: logits = h @ aW2^T + ab2 ; register softmax over K=16; weighted vp sum
    {
        float acc[8][4];
        mma_gemm(sm, acc);
#pragma unroll
        for (int nt = 0; nt < 8; nt++) {
            int ca = n0 + nt*8 + 2*ct;
            int ra0 = r0 + g, ra1 = ra0 + 8;
            float b0 = __ldg(&ab2[ca]), b1 = __ldg(&ab2[ca+1]);
            float l00 = acc[nt][0] + b0, l01 = acc[nt][1] + b1;
            float l10 = acc[nt][2] + b0, l11 = acc[nt][3] + b1;
            float m0 = redmax(fmaxf(l00, l10));
            float m1 = redmax(fmaxf(l01, l11));
            float e00 = __expf(l00 - m0), e10 = __expf(l10 - m0);
            float e01 = __expf(l01 - m1), e11 = __expf(l11 - m1);
            float s0 = redsum(e00 + e10);
            float s1 = redsum(e01 + e11);
            float2 vpa = *(const float2*)&sVp[ra0*132 + ca];
            float2 vpb = *(const float2*)&sVp[ra1*132 + ca];
            float w0 = redsum(fmaf(e00, vpa.x, e10 * vpb.x));
            float w1 = redsum(fmaf(e01, vpa.y, e11 * vpb.y));
            if (g == 0)
                *(float2*)&sOut[qi*128 + ca] = make_float2(w0 / s0, w1 / s1);
        }
        __syncthreads();
    }

    // final: out = sOut @ Wout^T (8x128 rows). Wout chunks staged in WHI area (fp32).
    {
        float* sWs = (float*)(sm + OFF_WHI);  // [128][17]
        float facc[2] = {0.f, 0.f};
        for (int kc = 0; kc < 128; kc += 16) {
            __syncthreads();
#pragma unroll
            for (int e = tid; e < 2048; e += 512) {
                int o = e >> 4, k = e & 15;
                sWs[o*17 + k] = Wout[o*128 + kc + k];
            }
            __syncthreads();
#pragma unroll
            for (int k = 0; k < 16; k++) {
#pragma unroll
                for (int u = 0; u < 2; u++) {
                    int it = tid + u*512;
                    int qr = it >> 7, o = it & 127;
                    facc[u] = fmaf(sOut[qr*128 + kc + k], sWs[o*17 + k], facc[u]);
                }
            }
        }
#pragma unroll
        for (int u = 0; u < 2; u++) {
            int it = tid + u*512;
            int qr = it >> 7, o = it & 127;
            out[((size_t)g0 + qr) * 128 + o] = facc[u];
        }
    }
}

// ---------------- launch ----------------
extern "C" void kernel_launch(void* const* d_in, const int* in_sizes, int n_in,
                              void* d_out, int out_size)
{
    const float* xyz   = (const float*)d_in[0];
    const float* feat  = (const float*)d_in[1];
    const float* Wq    = (const float*)d_in[2];
    const float* Wk    = (const float*)d_in[3];
    const float* Wv    = (const float*)d_in[4];
    const float* pW1   = (const float*)d_in[5];
    const float* pb1   = (const float*)d_in[6];
    const float* pg    = (const float*)d_in[7];
    const float* pbeta = (const float*)d_in[8];
    const float* pmean = (const float*)d_in[9];
    const float* pvar  = (const float*)d_in[10];
    const float* pW2   = (const float*)d_in[11];
    const float* pb2   = (const float*)d_in[12];
    const float* aW1   = (const float*)d_in[13];
    const float* ab1   = (const float*)d_in[14];
    const float* ag    = (const float*)d_in[15];
    const float* abeta = (const float*)d_in[16];
    const float* amean = (const float*)d_in[17];
    const float* avar  = (const float*)d_in[18];
    const float* aW2   = (const float*)d_in[19];
    const float* ab2   = (const float*)d_in[20];
    const float* Wout  = (const float*)d_in[21];
    float* out = (float*)d_out;

    cudaFuncSetAttribute((const void*)knn_kernel,
                         cudaFuncAttributeMaxDynamicSharedMemorySize, KNN_SMEM);
    cudaFuncSetAttribute((const void*)qkv_kernel,
                         cudaFuncAttributeMaxDynamicSharedMemorySize, QKV_SMEM);
    cudaFuncSetAttribute((const void*)main_kernel,
                         cudaFuncAttributeMaxDynamicSharedMemorySize, MAIN_SMEM);

    fold_kernel<<<1, 512>>>(pW1, pb1, pg, pbeta, pmean, pvar,
                            aW1, ab1, ag, abeta, amean, avar);
    knn_kernel<<<(BB*NN)/64, 256, KNN_SMEM>>>(xyz);
    qkv_kernel<<<(BB*NN)/128, 512, QKV_SMEM>>>(feat, Wq, Wk, Wv);
    main_kernel<<<(BB*NN)/8, 512, MAIN_SMEM>>>(xyz, pW2, pb2, aW2, ab2, Wout, out);
}